// round 13
// baseline (speedup 1.0000x reference)
#include <cuda_runtime.h>
#include <cuda_bf16.h>
#include <cstdint>

#define Nn 4096
#define Dd 256
#define Ss 32
#define Kk 4
#define CAP 256
#define COEFF 0.03125f   /* S/(N*EPS^2) = 32/(4096*0.25) */
#define ETA 0.5f

// ---------------- scratch (no allocs allowed) ----------------
__device__ unsigned short g_Lb[(size_t)Nn*Nn];   // bf16 L (32MB)
__device__ unsigned short g_Hb[(size_t)Dd*Nn];   // bf16 H^T  [d][node]
__device__ unsigned short g_Hob[(size_t)Dd*Nn];  // bf16 Hout^T [d][node]
__device__ float g_Zt[Kk*Nn*Ss];
__device__ float g_MinvZt[Kk*Nn*Ss];
__device__ float g_Zat[Kk*Nn*Ss];
__device__ float g_Mpart[16*Kk*Ss*Ss];
__device__ float g_Minv[Kk*Ss*Ss];
__device__ float g_Wt[Kk*Ss*Dd];
__device__ int   g_nbr[Nn*CAP];
__device__ int   g_cnt[Nn];
__device__ float g_aggT[Nn*Dd];
__device__ float g_LH[Nn*Dd];
__device__ float g_part[128];
__device__ float g_orth[10];

__device__ __forceinline__ uint32_t smem_u32(const void* p) {
    uint32_t a;
    asm("{ .reg .u64 t; cvta.to.shared.u64 t, %1; cvt.u32.u64 %0, t; }" : "=r"(a) : "l"(p));
    return a;
}
__device__ __forceinline__ void cp16(uint32_t dst, const void* src) {
    asm volatile("cp.async.cg.shared.global [%0], [%1], 16;" :: "r"(dst), "l"(src) : "memory");
}
#define CP_COMMIT() asm volatile("cp.async.commit_group;" ::: "memory")
template<int N> __device__ __forceinline__ void cp_wait() {
    asm volatile("cp.async.wait_group %0;" :: "n"(N) : "memory");
}
__device__ __forceinline__ void ldm_x4(uint32_t (&r)[4], uint32_t addr) {
    asm volatile("ldmatrix.sync.aligned.m8n8.x4.shared.b16 {%0,%1,%2,%3}, [%4];"
        : "=r"(r[0]), "=r"(r[1]), "=r"(r[2]), "=r"(r[3]) : "r"(addr));
}
__device__ __forceinline__ void mma_bf16(float (&c)[4],
                                         uint32_t a0, uint32_t a1, uint32_t a2, uint32_t a3,
                                         uint32_t b0, uint32_t b1) {
    asm volatile(
        "mma.sync.aligned.m16n8k16.row.col.f32.bf16.bf16.f32 "
        "{%0,%1,%2,%3},{%4,%5,%6,%7},{%8,%9},{%0,%1,%2,%3};"
        : "+f"(c[0]), "+f"(c[1]), "+f"(c[2]), "+f"(c[3])
        : "r"(a0), "r"(a1), "r"(a2), "r"(a3), "r"(b0), "r"(b1));
}
__device__ __forceinline__ unsigned short bf16b(float x) {
    __nv_bfloat16 h = __float2bfloat16_rn(x);
    return *reinterpret_cast<unsigned short*>(&h);
}

// ================= prep kernels =================
__global__ void k_cvtLb(const float* __restrict__ L) {
    size_t i = ((size_t)blockIdx.x*256 + threadIdx.x)*8;
    float4 v0 = *(const float4*)(L + i);
    float4 v1 = *(const float4*)(L + i + 4);
    uint32_t p[4];
    p[0] = (uint32_t)bf16b(v0.x) | ((uint32_t)bf16b(v0.y) << 16);
    p[1] = (uint32_t)bf16b(v0.z) | ((uint32_t)bf16b(v0.w) << 16);
    p[2] = (uint32_t)bf16b(v1.x) | ((uint32_t)bf16b(v1.y) << 16);
    p[3] = (uint32_t)bf16b(v1.z) | ((uint32_t)bf16b(v1.w) << 16);
    *(uint4*)(g_Lb + i) = make_uint4(p[0], p[1], p[2], p[3]);
}

__global__ void k_tr(const float* __restrict__ src, unsigned short* __restrict__ dst) {
    __shared__ unsigned short t[64][66];
    int nb = blockIdx.x*64, db = blockIdx.y*64;
    int tid = threadIdx.x;
#pragma unroll
    for (int i = 0; i < 16; i++) {
        int idx = tid + i*256;
        int r = idx >> 6, c = idx & 63;
        t[c][r] = bf16b(src[(size_t)(nb + r)*Dd + db + c]);
    }
    __syncthreads();
#pragma unroll
    for (int i = 0; i < 16; i++) {
        int idx = tid + i*256;
        int r = idx >> 6, c = idx & 63;
        dst[(size_t)(db + r)*Nn + nb + c] = t[r][c];
    }
}

// ================= bf16 mma GEMM: C[4096x256] = L @ B (BM=128, R11 config) =======
#define BM 128
#define BN 64
#define BK 32
#define APITCH 80
#define BPITCH 80
#define A_BYTES (BM*APITCH)
#define B_BYTES (BN*BPITCH)
#define STG_B (A_BYTES + B_BYTES)
#define NSTG 4
#define SMEMB (NSTG*STG_B)
#define NT (Nn/BK)

template<int MODE>
__global__ void __launch_bounds__(256, 1) k_gemm(const float* __restrict__ Hd) {
    extern __shared__ char sm[];
    int tid = threadIdx.x;
    int lane = tid & 31, warp = tid >> 5;
    int warpM = (warp & 3)*32, warpN = (warp >> 2)*32;
    int gid = lane >> 2, t4 = lane & 3;
    int bm = blockIdx.x*BM, bn = blockIdx.y*BN;
    const unsigned short* A  = g_Lb;
    const unsigned short* Bt = MODE ? g_Hob : g_Hb;
    uint32_t sb = smem_u32(sm);

    float acc[2][4][4] = {};

    int lr = (lane & 7) + ((lane >> 3) & 1)*8;
    int lc = (lane >> 4)*16;
    int bnr = (lane & 7) + ((lane >> 4) & 1)*8;
    int bco = ((lane >> 3) & 1)*16;

    int am0 = tid >> 2, ac0 = tid & 3;
    int am1 = (tid + 256) >> 2, ac1 = (tid + 256) & 3;
    int bm2 = tid >> 2, bc2 = tid & 3;

#define LOAD_STAGE(s, k0) do { \
    uint32_t base = sb + (s)*STG_B; \
    cp16(base + am0*APITCH + ac0*16, A + (size_t)(bm + am0)*Nn + (k0) + ac0*8); \
    cp16(base + am1*APITCH + ac1*16, A + (size_t)(bm + am1)*Nn + (k0) + ac1*8); \
    cp16(base + A_BYTES + bm2*BPITCH + bc2*16, Bt + (size_t)(bn + bm2)*Nn + (k0) + bc2*8); \
} while (0)

    LOAD_STAGE(0, 0);    CP_COMMIT();
    LOAD_STAGE(1, BK);   CP_COMMIT();
    LOAD_STAGE(2, 2*BK); CP_COMMIT();

    for (int kt = 0; kt < NT; kt++) {
        cp_wait<2>();
        __syncthreads();
        if (kt + 3 < NT) LOAD_STAGE((kt+3) & 3, (kt+3)*BK);
        CP_COMMIT();

        uint32_t As = sb + (kt & 3)*STG_B;
        uint32_t Bs = As + A_BYTES;
#pragma unroll
        for (int ks = 0; ks < 2; ks++) {
            uint32_t a0[4], a1[4], b0[4], b1[4];
            ldm_x4(a0, As + (warpM + lr)*APITCH + ks*32 + lc);
            ldm_x4(a1, As + (warpM + 16 + lr)*APITCH + ks*32 + lc);
            ldm_x4(b0, Bs + (warpN + bnr)*BPITCH + ks*32 + bco);
            ldm_x4(b1, Bs + (warpN + 16 + bnr)*BPITCH + ks*32 + bco);
            mma_bf16(acc[0][0], a0[0], a0[1], a0[2], a0[3], b0[0], b0[1]);
            mma_bf16(acc[1][0], a1[0], a1[1], a1[2], a1[3], b0[0], b0[1]);
            mma_bf16(acc[0][1], a0[0], a0[1], a0[2], a0[3], b0[2], b0[3]);
            mma_bf16(acc[1][1], a1[0], a1[1], a1[2], a1[3], b0[2], b0[3]);
            mma_bf16(acc[0][2], a0[0], a0[1], a0[2], a0[3], b1[0], b1[1]);
            mma_bf16(acc[1][2], a1[0], a1[1], a1[2], a1[3], b1[0], b1[1]);
            mma_bf16(acc[0][3], a0[0], a0[1], a0[2], a0[3], b1[2], b1[3]);
            mma_bf16(acc[1][3], a1[0], a1[1], a1[2], a1[3], b1[2], b1[3]);
        }
    }

    if (MODE == 0) {
#pragma unroll
        for (int mt = 0; mt < 2; mt++)
#pragma unroll
            for (int nt = 0; nt < 4; nt++) {
                int r0 = bm + warpM + mt*16 + gid;
                int c0 = bn + warpN + nt*8 + 2*t4;
                *(float2*)&g_LH[(size_t)r0*Dd + c0] = make_float2(acc[mt][nt][0], acc[mt][nt][1]);
                *(float2*)&g_LH[(size_t)(r0+8)*Dd + c0] = make_float2(acc[mt][nt][2], acc[mt][nt][3]);
            }
    } else {
        __shared__ float red[256];
        float part = 0.f;
#pragma unroll
        for (int mt = 0; mt < 2; mt++)
#pragma unroll
            for (int nt = 0; nt < 4; nt++) {
                int r0 = bm + warpM + mt*16 + gid;
                int c0 = bn + warpN + nt*8 + 2*t4;
                float2 h0 = *(const float2*)&Hd[(size_t)r0*Dd + c0];
                float2 h1 = *(const float2*)&Hd[(size_t)(r0+8)*Dd + c0];
                part += acc[mt][nt][0]*h0.x + acc[mt][nt][1]*h0.y
                      + acc[mt][nt][2]*h1.x + acc[mt][nt][3]*h1.y;
            }
        red[tid] = part;
        __syncthreads();
        for (int s = 128; s > 0; s >>= 1) {
            if (tid < s) red[tid] += red[tid + s];
            __syncthreads();
        }
        if (tid == 0) g_part[blockIdx.y*gridDim.x + blockIdx.x] = red[0];
    }
}

// ================= small kernels =================
__global__ void k_Z(const float* __restrict__ H, const float* __restrict__ U) {
    __shared__ float Ush[Dd*Ss];
    __shared__ float Hsh[128*17];
    int k = blockIdx.y;
    for (int idx = threadIdx.x; idx < Dd*Ss; idx += 128)
        Ush[idx] = U[k*Dd*Ss + idx];
    int nb = blockIdx.x*128;
    float acc[Ss];
#pragma unroll
    for (int s = 0; s < Ss; s++) acc[s] = 0.f;
    for (int d0 = 0; d0 < Dd; d0 += 16) {
        __syncthreads();
#pragma unroll
        for (int i = 0; i < 16; i++) {
            int idx = threadIdx.x + i*128;
            int node = idx >> 4, col = idx & 15;
            Hsh[node*17 + col] = H[(size_t)(nb + node)*Dd + d0 + col];
        }
        __syncthreads();
#pragma unroll
        for (int d = 0; d < 16; d++) {
            float h = Hsh[threadIdx.x*17 + d];
            const float* up = &Ush[(d0 + d)*Ss];
#pragma unroll
            for (int s = 0; s < Ss; s++) acc[s] += up[s]*h;
        }
    }
    float* zp = g_Zt + ((size_t)k*Nn + nb + threadIdx.x)*Ss;
#pragma unroll
    for (int s = 0; s < Ss; s++) zp[s] = acc[s];
}

__global__ void k_M() {
    int k = blockIdx.y;
    int chunk = blockIdx.x;
    __shared__ float zsh[32][33];
    int s = threadIdx.x / 32, t = threadIdx.x % 32;
    float acc = 0.f;
    int nbase = chunk*256;
    for (int n0 = 0; n0 < 256; n0 += 32) {
        zsh[threadIdx.x/32][threadIdx.x%32] =
            g_Zt[((size_t)k*Nn + nbase + n0 + threadIdx.x/32)*Ss + (threadIdx.x%32)];
        __syncthreads();
#pragma unroll
        for (int n = 0; n < 32; n++) acc += zsh[n][s]*zsh[n][t];
        __syncthreads();
    }
    g_Mpart[((size_t)chunk*Kk + k)*1024 + s*32 + t] = acc;
}

// fused Msum + register/shuffle Gauss-Jordan. 1 block, 256 threads.
__global__ void k_invF() {
    __shared__ float Msh[Kk*1024];
    int tid = threadIdx.x;
#pragma unroll
    for (int q = 0; q < Kk; q++) {
        for (int st = tid; st < 1024; st += 256) {
            float m = 0.f;
#pragma unroll
            for (int c = 0; c < 16; c++)
                m += g_Mpart[(size_t)(c*Kk + q)*1024 + st];
            int s = st >> 5, t = st & 31;
            Msh[q*1024 + st] = COEFF*m + (s == t ? 1.f : 0.f);
        }
    }
    __syncthreads();
    if (tid < 128) {
        int k = tid >> 5, j = tid & 31;
        float a[32], b[32];
#pragma unroll
        for (int r = 0; r < 32; r++) {
            a[r] = Msh[k*1024 + r*32 + j];
            b[r] = (r == j) ? 1.f : 0.f;
        }
#pragma unroll
        for (int p = 0; p < 32; p++) {
            float piv = __shfl_sync(0xffffffffu, a[p], p);
            float ip = 1.f / piv;
            a[p] *= ip; b[p] *= ip;
#pragma unroll
            for (int r = 0; r < 32; r++) {
                if (r == p) continue;
                float f = __shfl_sync(0xffffffffu, a[r], p);
                a[r] -= f*a[p];
                b[r] -= f*b[p];
            }
        }
#pragma unroll
        for (int r = 0; r < 32; r++) g_Minv[(k*32 + r)*32 + j] = b[r];
    }
}

__global__ void k_MinvZ() {
    int k = blockIdx.y;
    __shared__ float MshT[1024];
    for (int idx = threadIdx.x; idx < 1024; idx += 256) {
        int t = idx >> 5, s2 = idx & 31;
        MshT[t*32 + s2] = g_Minv[(k*Ss + s2)*Ss + t];
    }
    __syncthreads();
    int w = threadIdx.x >> 5, lane = threadIdx.x & 31;
#pragma unroll
    for (int ii = 0; ii < 4; ii++) {
        int n = blockIdx.x*32 + w*4 + ii;
        float z = g_Zt[((size_t)k*Nn + n)*Ss + lane];
        float acc = 0.f;
#pragma unroll
        for (int t = 0; t < 32; t++)
            acc += MshT[t*32 + lane] * __shfl_sync(0xffffffffu, z, t);
        g_MinvZt[((size_t)k*Nn + n)*Ss + lane] = acc;
    }
}

__global__ void k_nbr(const float* __restrict__ adj) {
    int warp = threadIdx.x / 32, lane = threadIdx.x % 32;
    int i = blockIdx.x*4 + warp;
    int base = 0;
    const float4* rowv = (const float4*)(adj + (size_t)i*Nn);
    unsigned mlt = (1u << lane) - 1u;
    int* nb = g_nbr + (size_t)i*CAP;
#pragma unroll 4
    for (int it = 0; it < 32; it++) {
        float4 v = rowv[it*32 + lane];
        unsigned b0 = __ballot_sync(0xffffffffu, v.x > 0.5f);
        unsigned b1 = __ballot_sync(0xffffffffu, v.y > 0.5f);
        unsigned b2 = __ballot_sync(0xffffffffu, v.z > 0.5f);
        unsigned b3 = __ballot_sync(0xffffffffu, v.w > 0.5f);
        int pre = __popc(b0 & mlt) + __popc(b1 & mlt) + __popc(b2 & mlt) + __popc(b3 & mlt);
        int col = it*128 + 4*lane;
        int o = base + pre;
        if (v.x > 0.5f) { if (o < CAP) nb[o] = col;     o++; }
        if (v.y > 0.5f) { if (o < CAP) nb[o] = col + 1; o++; }
        if (v.z > 0.5f) { if (o < CAP) nb[o] = col + 2; o++; }
        if (v.w > 0.5f) { if (o < CAP) nb[o] = col + 3; o++; }
        base += __popc(b0) + __popc(b1) + __popc(b2) + __popc(b3);
    }
    if (lane == 0) g_cnt[i] = base < CAP ? base : CAP;
}

// group-of-32 sparse attention: lane=neighbor for scores, lane=s for V.
__global__ void k_attn() {
    int warp = threadIdx.x >> 5, lane = threadIdx.x & 31;
    int i = blockIdx.x*4 + warp;
    int k = blockIdx.y;
    const float* Zk = g_Zt + (size_t)k*Nn*Ss;
    const float* Mk = g_MinvZt + (size_t)k*Nn*Ss;
    float4 q4[8];
    const float4* qrow = (const float4*)(Zk + (size_t)i*Ss);
#pragma unroll
    for (int c = 0; c < 8; c++) q4[c] = qrow[c];
    int cnt = g_cnt[i];
    const int* nb = g_nbr + (size_t)i*CAP;
    float m = -3.0e38f, l = 0.f, o = 0.f;
    for (int t0 = 0; t0 < cnt; t0 += 32) {
        int t = t0 + lane;
        bool valid = (t < cnt);
        int j = valid ? nb[t] : 0;
        float p = -3.0e38f;
        if (valid) {
            const float4* kv = (const float4*)(Mk + (size_t)j*Ss);
            float s = 0.f;
#pragma unroll
            for (int c = 0; c < 8; c++) {
                float4 v = kv[c];
                s += q4[c].x*v.x + q4[c].y*v.y + q4[c].z*v.z + q4[c].w*v.w;
            }
            p = s;
        }
        float gmax = p;
#pragma unroll
        for (int off = 16; off > 0; off >>= 1)
            gmax = fmaxf(gmax, __shfl_xor_sync(0xffffffffu, gmax, off));
        float mn = fmaxf(m, gmax);
        float e = valid ? __expf(p - mn) : 0.f;
        float esum = e;
#pragma unroll
        for (int off = 16; off > 0; off >>= 1)
            esum += __shfl_xor_sync(0xffffffffu, esum, off);
        float sc = __expf(m - mn);
        float oadd = 0.f;
        int lim = cnt - t0; if (lim > 32) lim = 32;
        for (int jj = 0; jj < lim; jj++) {
            float a = __shfl_sync(0xffffffffu, e, jj);
            int jv = __shfl_sync(0xffffffffu, j, jj);
            oadd += a * Zk[(size_t)jv*Ss + lane];
        }
        o = o*sc + oadd;
        l = l*sc + esum;
        m = mn;
    }
    g_Zat[((size_t)k*Nn + i)*Ss + lane] = o / l;
}

__global__ void k_W(const float* __restrict__ U) {
    int k = blockIdx.x, d = threadIdx.x;
    __shared__ float Msh[Ss*Ss];
    for (int idx = threadIdx.x; idx < Ss*Ss; idx += 256)
        Msh[idx] = g_Minv[k*Ss*Ss + idx];
    __syncthreads();
    float acc[Ss];
#pragma unroll
    for (int t = 0; t < Ss; t++) acc[t] = 0.f;
    for (int s = 0; s < Ss; s++) {
        float u = U[((size_t)k*Dd + d)*Ss + s];
#pragma unroll
        for (int t = 0; t < Ss; t++) acc[t] += u * Msh[s*Ss + t];
    }
#pragma unroll
    for (int t = 0; t < Ss; t++) g_Wt[((size_t)k*Ss + t)*Dd + d] = acc[t];
}

__global__ void k_agg() {
    __shared__ float zat[32][128];
    int n0 = blockIdx.x*32;
    for (int idx = threadIdx.x; idx < 32*128; idx += 256) {
        int nn = idx / 128, kt = idx % 128;
        int k = kt / 32, t = kt % 32;
        zat[nn][kt] = g_Zat[((size_t)k*Nn + n0 + nn)*Ss + t];
    }
    __syncthreads();
    int d = threadIdx.x;
    float acc[32];
#pragma unroll
    for (int nn = 0; nn < 32; nn++) acc[nn] = 0.f;
    for (int kt = 0; kt < 128; kt++) {
        float w = g_Wt[(size_t)kt*Dd + d];
#pragma unroll
        for (int nn = 0; nn < 32; nn++) acc[nn] += w * zat[nn][kt];
    }
#pragma unroll
    for (int nn = 0; nn < 32; nn++) g_aggT[(size_t)(n0 + nn)*Dd + d] = acc[nn];
}

__global__ void k_thresh_tr(const float* __restrict__ H,
                            const float* __restrict__ lam,
                            const float* __restrict__ thrArr,
                            float* __restrict__ out) {
    __shared__ unsigned short tsh[64][66];
    int nb = blockIdx.x*64, db = blockIdx.y*64;
    float la = ETA*lam[0];
#pragma unroll
    for (int i = 0; i < 16; i++) {
        int idx = threadIdx.x + i*256;
        int r = idx >> 6, c = idx & 63;
        size_t g = (size_t)(nb + r)*Dd + db + c;
        float hh = H[g] + ETA*g_aggT[g] - la*g_LH[g];
        float a = fabsf(hh) - thrArr[db + c];
        float v = a > 0.f ? copysignf(a, hh) : 0.f;
        out[g] = v;
        tsh[c][r] = bf16b(v);
    }
    __syncthreads();
#pragma unroll
    for (int i = 0; i < 16; i++) {
        int idx = threadIdx.x + i*256;
        int r = idx >> 6, c = idx & 63;
        g_Hob[(size_t)(db + r)*Nn + nb + c] = tsh[r][c];
    }
}

__global__ void k_orth(const float* __restrict__ U) {
    int b = blockIdx.x, k = 0;
    while (b >= Kk - k) { b -= Kk - k; k++; }
    int l = k + b;
    int s = threadIdx.x / 32, e = threadIdx.x % 32;
    __shared__ float Uk[64][32], Ul[64][32];
    __shared__ float red[1024];
    float acc = 0.f;
    for (int d0 = 0; d0 < Dd; d0 += 64) {
        for (int idx = threadIdx.x; idx < 64*32; idx += 1024) {
            Uk[idx/32][idx%32] = U[((size_t)k*Dd + d0 + idx/32)*Ss + idx%32];
            Ul[idx/32][idx%32] = U[((size_t)l*Dd + d0 + idx/32)*Ss + idx%32];
        }
        __syncthreads();
#pragma unroll
        for (int dd = 0; dd < 64; dd++) acc += Uk[dd][s]*Ul[dd][e];
        __syncthreads();
    }
    float c;
    if (k == l) { float dl = acc - (s == e ? 1.f : 0.f); c = dl*dl; }
    else c = acc*acc;
    red[threadIdx.x] = c;
    __syncthreads();
    for (int st = 512; st > 0; st >>= 1) {
        if (threadIdx.x < st) red[threadIdx.x] += red[threadIdx.x + st];
        __syncthreads();
    }
    if (threadIdx.x == 0) g_orth[blockIdx.x] = red[0];
}

__global__ void k_scalars(float* __restrict__ out) {
    if (threadIdx.x == 0) {
        float o = 0.f;
        for (int i = 0; i < 10; i++) o += g_orth[i];
        out[(size_t)Nn*Dd] = o;
        float ls = 0.f;
        for (int i = 0; i < 128; i++) ls += g_part[i];
        out[(size_t)Nn*Dd + 1] = ls;
    }
}

// ---------------- launch (single stream; gemm0 is 4th kernel for ncu) ----------
extern "C" void kernel_launch(void* const* d_in, const int* in_sizes, int n_in,
                              void* d_out, int out_size) {
    const float* H   = (const float*)d_in[0];
    const float* adj = (const float*)d_in[1];
    const float* L   = (const float*)d_in[2];
    const float* U   = (const float*)d_in[3];
    const float* lam = (const float*)d_in[4];
    const float* thr = (const float*)d_in[5];
    float* out = (float*)d_out;

    static int init = 0;
    if (!init) {
        cudaFuncSetAttribute(k_gemm<0>, cudaFuncAttributeMaxDynamicSharedMemorySize, SMEMB);
        cudaFuncSetAttribute(k_gemm<1>, cudaFuncAttributeMaxDynamicSharedMemorySize, SMEMB);
        init = 1;
    }

    unsigned short* hbptr;
    cudaGetSymbolAddress((void**)&hbptr, g_Hb);

    k_cvtLb<<<Nn*Nn/8/256, 256>>>(L);                       // 1
    k_tr<<<dim3(Nn/64, Dd/64), 256>>>(H, hbptr);            // 2
    k_Z<<<dim3(Nn/128, Kk), 128>>>(H, U);                   // 3
    k_gemm<0><<<dim3(Nn/BM, Dd/BN), 256, SMEMB>>>(nullptr); // 4  <- ncu window
    k_M<<<dim3(16, Kk), 1024>>>();                          // 5
    k_invF<<<1, 256>>>();                                   // 6
    k_MinvZ<<<dim3(Nn/32, Kk), 256>>>();                    // 7
    k_nbr<<<Nn/4, 128>>>(adj);                              // 8
    k_attn<<<dim3(Nn/4, Kk), 128>>>();                      // 9
    k_W<<<Kk, 256>>>(U);                                    // 10
    k_agg<<<Nn/32, 256>>>();                                // 11
    k_thresh_tr<<<dim3(Nn/64, Dd/64), 256>>>(H, lam, thr, out); // 12
    k_gemm<1><<<dim3(Nn/BM, Dd/BN), 256, SMEMB>>>(out);     // 13
    k_orth<<<10, 1024>>>(U);                                // 14
    k_scalars<<<1, 256>>>(out);                             // 15
}

// round 14
// speedup vs baseline: 1.0247x; 1.0247x over previous
#include <cuda_runtime.h>
#include <cuda_bf16.h>
#include <cstdint>

#define Nn 4096
#define Dd 256
#define Ss 32
#define Kk 4
#define CAP 256
#define COEFF 0.03125f   /* S/(N*EPS^2) = 32/(4096*0.25) */
#define ETA 0.5f

// ---------------- scratch (no allocs allowed) ----------------
__device__ unsigned short g_Lb[(size_t)Nn*Nn];   // bf16 L (32MB)
__device__ unsigned short g_Hb[(size_t)Dd*Nn];   // bf16 H^T  [d][node]
__device__ unsigned short g_Hob[(size_t)Dd*Nn];  // bf16 Hout^T [d][node]
__device__ float g_Zt[Kk*Nn*Ss];
__device__ float g_MinvZt[Kk*Nn*Ss];
__device__ float g_Zat[Kk*Nn*Ss];
__device__ float g_Mpart[16*Kk*Ss*Ss];
__device__ float g_Minv[Kk*Ss*Ss];
__device__ float g_Wt[Kk*Ss*Dd];
__device__ int   g_nbr[Nn*CAP];
__device__ int   g_cnt[Nn];
__device__ float g_aggT[Nn*Dd];
__device__ float g_LH[Nn*Dd];
__device__ float g_part[128];
__device__ float g_orth[10];

__device__ __forceinline__ uint32_t smem_u32(const void* p) {
    uint32_t a;
    asm("{ .reg .u64 t; cvta.to.shared.u64 t, %1; cvt.u32.u64 %0, t; }" : "=r"(a) : "l"(p));
    return a;
}
__device__ __forceinline__ void cp16(uint32_t dst, const void* src) {
    asm volatile("cp.async.cg.shared.global [%0], [%1], 16;" :: "r"(dst), "l"(src) : "memory");
}
#define CP_COMMIT() asm volatile("cp.async.commit_group;" ::: "memory")
template<int N> __device__ __forceinline__ void cp_wait() {
    asm volatile("cp.async.wait_group %0;" :: "n"(N) : "memory");
}
__device__ __forceinline__ void ldm_x4(uint32_t (&r)[4], uint32_t addr) {
    asm volatile("ldmatrix.sync.aligned.m8n8.x4.shared.b16 {%0,%1,%2,%3}, [%4];"
        : "=r"(r[0]), "=r"(r[1]), "=r"(r[2]), "=r"(r[3]) : "r"(addr));
}
__device__ __forceinline__ void mma_bf16(float (&c)[4],
                                         uint32_t a0, uint32_t a1, uint32_t a2, uint32_t a3,
                                         uint32_t b0, uint32_t b1) {
    asm volatile(
        "mma.sync.aligned.m16n8k16.row.col.f32.bf16.bf16.f32 "
        "{%0,%1,%2,%3},{%4,%5,%6,%7},{%8,%9},{%0,%1,%2,%3};"
        : "+f"(c[0]), "+f"(c[1]), "+f"(c[2]), "+f"(c[3])
        : "r"(a0), "r"(a1), "r"(a2), "r"(a3), "r"(b0), "r"(b1));
}
__device__ __forceinline__ unsigned short bf16b(float x) {
    __nv_bfloat16 h = __float2bfloat16_rn(x);
    return *reinterpret_cast<unsigned short*>(&h);
}

// ================= prep kernels =================
__global__ void k_cvtLb(const float* __restrict__ L) {
    size_t i = ((size_t)blockIdx.x*256 + threadIdx.x)*8;
    float4 v0 = *(const float4*)(L + i);
    float4 v1 = *(const float4*)(L + i + 4);
    uint32_t p[4];
    p[0] = (uint32_t)bf16b(v0.x) | ((uint32_t)bf16b(v0.y) << 16);
    p[1] = (uint32_t)bf16b(v0.z) | ((uint32_t)bf16b(v0.w) << 16);
    p[2] = (uint32_t)bf16b(v1.x) | ((uint32_t)bf16b(v1.y) << 16);
    p[3] = (uint32_t)bf16b(v1.z) | ((uint32_t)bf16b(v1.w) << 16);
    *(uint4*)(g_Lb + i) = make_uint4(p[0], p[1], p[2], p[3]);
}

__global__ void k_tr(const float* __restrict__ src, unsigned short* __restrict__ dst) {
    __shared__ unsigned short t[64][66];
    int nb = blockIdx.x*64, db = blockIdx.y*64;
    int tid = threadIdx.x;
#pragma unroll
    for (int i = 0; i < 16; i++) {
        int idx = tid + i*256;
        int r = idx >> 6, c = idx & 63;
        t[c][r] = bf16b(src[(size_t)(nb + r)*Dd + db + c]);
    }
    __syncthreads();
#pragma unroll
    for (int i = 0; i < 16; i++) {
        int idx = tid + i*256;
        int r = idx >> 6, c = idx & 63;
        dst[(size_t)(db + r)*Nn + nb + c] = t[r][c];
    }
}

// ================= bf16 mma GEMM: C[4096x256] = L @ B =================
// BM=128, register-hoisted fragments (8 independent ldmatrix before 16 mma).
#define BM 128
#define BN 64
#define BK 32
#define APITCH 80
#define BPITCH 80
#define A_BYTES (BM*APITCH)
#define B_BYTES (BN*BPITCH)
#define STG_B (A_BYTES + B_BYTES)
#define NSTG 4
#define SMEMB (NSTG*STG_B)
#define NT (Nn/BK)

template<int MODE>
__global__ void __launch_bounds__(256, 1) k_gemm(const float* __restrict__ Hd) {
    extern __shared__ char sm[];
    int tid = threadIdx.x;
    int lane = tid & 31, warp = tid >> 5;
    int warpM = (warp & 3)*32, warpN = (warp >> 2)*32;
    int gid = lane >> 2, t4 = lane & 3;
    int bm = blockIdx.x*BM, bn = blockIdx.y*BN;
    const unsigned short* A  = g_Lb;
    const unsigned short* Bt = MODE ? g_Hob : g_Hb;
    uint32_t sb = smem_u32(sm);

    float acc[2][4][4] = {};

    int lr = (lane & 7) + ((lane >> 3) & 1)*8;
    int lc = (lane >> 4)*16;
    int bnr = (lane & 7) + ((lane >> 4) & 1)*8;
    int bco = ((lane >> 3) & 1)*16;

    int am0 = tid >> 2, ac0 = tid & 3;
    int am1 = (tid + 256) >> 2, ac1 = (tid + 256) & 3;
    int bm2 = tid >> 2, bc2 = tid & 3;

#define LOAD_STAGE(s, k0) do { \
    uint32_t base = sb + (s)*STG_B; \
    cp16(base + am0*APITCH + ac0*16, A + (size_t)(bm + am0)*Nn + (k0) + ac0*8); \
    cp16(base + am1*APITCH + ac1*16, A + (size_t)(bm + am1)*Nn + (k0) + ac1*8); \
    cp16(base + A_BYTES + bm2*BPITCH + bc2*16, Bt + (size_t)(bn + bm2)*Nn + (k0) + bc2*8); \
} while (0)

    LOAD_STAGE(0, 0);    CP_COMMIT();
    LOAD_STAGE(1, BK);   CP_COMMIT();
    LOAD_STAGE(2, 2*BK); CP_COMMIT();

    for (int kt = 0; kt < NT; kt++) {
        cp_wait<2>();
        __syncthreads();
        if (kt + 3 < NT) LOAD_STAGE((kt+3) & 3, (kt+3)*BK);
        CP_COMMIT();

        uint32_t As = sb + (kt & 3)*STG_B;
        uint32_t Bs = As + A_BYTES;

        // hoist ALL fragment loads (8 independent ldmatrix) before the 16 mma
        uint32_t a0[2][4], a1[2][4], b0[2][4], b1[2][4];
#pragma unroll
        for (int ks = 0; ks < 2; ks++) {
            ldm_x4(a0[ks], As + (warpM + lr)*APITCH + ks*32 + lc);
            ldm_x4(a1[ks], As + (warpM + 16 + lr)*APITCH + ks*32 + lc);
            ldm_x4(b0[ks], Bs + (warpN + bnr)*BPITCH + ks*32 + bco);
            ldm_x4(b1[ks], Bs + (warpN + 16 + bnr)*BPITCH + ks*32 + bco);
        }
#pragma unroll
        for (int ks = 0; ks < 2; ks++) {
            mma_bf16(acc[0][0], a0[ks][0], a0[ks][1], a0[ks][2], a0[ks][3], b0[ks][0], b0[ks][1]);
            mma_bf16(acc[1][0], a1[ks][0], a1[ks][1], a1[ks][2], a1[ks][3], b0[ks][0], b0[ks][1]);
            mma_bf16(acc[0][1], a0[ks][0], a0[ks][1], a0[ks][2], a0[ks][3], b0[ks][2], b0[ks][3]);
            mma_bf16(acc[1][1], a1[ks][0], a1[ks][1], a1[ks][2], a1[ks][3], b0[ks][2], b0[ks][3]);
            mma_bf16(acc[0][2], a0[ks][0], a0[ks][1], a0[ks][2], a0[ks][3], b1[ks][0], b1[ks][1]);
            mma_bf16(acc[1][2], a1[ks][0], a1[ks][1], a1[ks][2], a1[ks][3], b1[ks][0], b1[ks][1]);
            mma_bf16(acc[0][3], a0[ks][0], a0[ks][1], a0[ks][2], a0[ks][3], b1[ks][2], b1[ks][3]);
            mma_bf16(acc[1][3], a1[ks][0], a1[ks][1], a1[ks][2], a1[ks][3], b1[ks][2], b1[ks][3]);
        }
    }

    if (MODE == 0) {
#pragma unroll
        for (int mt = 0; mt < 2; mt++)
#pragma unroll
            for (int nt = 0; nt < 4; nt++) {
                int r0 = bm + warpM + mt*16 + gid;
                int c0 = bn + warpN + nt*8 + 2*t4;
                *(float2*)&g_LH[(size_t)r0*Dd + c0] = make_float2(acc[mt][nt][0], acc[mt][nt][1]);
                *(float2*)&g_LH[(size_t)(r0+8)*Dd + c0] = make_float2(acc[mt][nt][2], acc[mt][nt][3]);
            }
    } else {
        __shared__ float red[256];
        float part = 0.f;
#pragma unroll
        for (int mt = 0; mt < 2; mt++)
#pragma unroll
            for (int nt = 0; nt < 4; nt++) {
                int r0 = bm + warpM + mt*16 + gid;
                int c0 = bn + warpN + nt*8 + 2*t4;
                float2 h0 = *(const float2*)&Hd[(size_t)r0*Dd + c0];
                float2 h1 = *(const float2*)&Hd[(size_t)(r0+8)*Dd + c0];
                part += acc[mt][nt][0]*h0.x + acc[mt][nt][1]*h0.y
                      + acc[mt][nt][2]*h1.x + acc[mt][nt][3]*h1.y;
            }
        red[tid] = part;
        __syncthreads();
        for (int s = 128; s > 0; s >>= 1) {
            if (tid < s) red[tid] += red[tid + s];
            __syncthreads();
        }
        if (tid == 0) g_part[blockIdx.y*gridDim.x + blockIdx.x] = red[0];
    }
}

// ================= small kernels =================
__global__ void k_Z(const float* __restrict__ H, const float* __restrict__ U) {
    __shared__ float Ush[Dd*Ss];
    __shared__ float Hsh[128*17];
    int k = blockIdx.y;
    for (int idx = threadIdx.x; idx < Dd*Ss; idx += 128)
        Ush[idx] = U[k*Dd*Ss + idx];
    int nb = blockIdx.x*128;
    float acc[Ss];
#pragma unroll
    for (int s = 0; s < Ss; s++) acc[s] = 0.f;
    for (int d0 = 0; d0 < Dd; d0 += 16) {
        __syncthreads();
#pragma unroll
        for (int i = 0; i < 16; i++) {
            int idx = threadIdx.x + i*128;
            int node = idx >> 4, col = idx & 15;
            Hsh[node*17 + col] = H[(size_t)(nb + node)*Dd + d0 + col];
        }
        __syncthreads();
#pragma unroll
        for (int d = 0; d < 16; d++) {
            float h = Hsh[threadIdx.x*17 + d];
            const float* up = &Ush[(d0 + d)*Ss];
#pragma unroll
            for (int s = 0; s < Ss; s++) acc[s] += up[s]*h;
        }
    }
    float* zp = g_Zt + ((size_t)k*Nn + nb + threadIdx.x)*Ss;
#pragma unroll
    for (int s = 0; s < Ss; s++) zp[s] = acc[s];
}

__global__ void k_M() {
    int k = blockIdx.y;
    int chunk = blockIdx.x;
    __shared__ float zsh[32][33];
    int s = threadIdx.x / 32, t = threadIdx.x % 32;
    float acc = 0.f;
    int nbase = chunk*256;
    for (int n0 = 0; n0 < 256; n0 += 32) {
        zsh[threadIdx.x/32][threadIdx.x%32] =
            g_Zt[((size_t)k*Nn + nbase + n0 + threadIdx.x/32)*Ss + (threadIdx.x%32)];
        __syncthreads();
#pragma unroll
        for (int n = 0; n < 32; n++) acc += zsh[n][s]*zsh[n][t];
        __syncthreads();
    }
    g_Mpart[((size_t)chunk*Kk + k)*1024 + s*32 + t] = acc;
}

// fused Msum + register/shuffle Gauss-Jordan. 1 block, 256 threads.
__global__ void k_invF() {
    __shared__ float Msh[Kk*1024];
    int tid = threadIdx.x;
#pragma unroll
    for (int q = 0; q < Kk; q++) {
        for (int st = tid; st < 1024; st += 256) {
            float m = 0.f;
#pragma unroll
            for (int c = 0; c < 16; c++)
                m += g_Mpart[(size_t)(c*Kk + q)*1024 + st];
            int s = st >> 5, t = st & 31;
            Msh[q*1024 + st] = COEFF*m + (s == t ? 1.f : 0.f);
        }
    }
    __syncthreads();
    if (tid < 128) {
        int k = tid >> 5, j = tid & 31;
        float a[32], b[32];
#pragma unroll
        for (int r = 0; r < 32; r++) {
            a[r] = Msh[k*1024 + r*32 + j];
            b[r] = (r == j) ? 1.f : 0.f;
        }
#pragma unroll
        for (int p = 0; p < 32; p++) {
            float piv = __shfl_sync(0xffffffffu, a[p], p);
            float ip = 1.f / piv;
            a[p] *= ip; b[p] *= ip;
#pragma unroll
            for (int r = 0; r < 32; r++) {
                if (r == p) continue;
                float f = __shfl_sync(0xffffffffu, a[r], p);
                a[r] -= f*a[p];
                b[r] -= f*b[p];
            }
        }
#pragma unroll
        for (int r = 0; r < 32; r++) g_Minv[(k*32 + r)*32 + j] = b[r];
    }
}

__global__ void k_MinvZ() {
    int k = blockIdx.y;
    __shared__ float MshT[1024];
    for (int idx = threadIdx.x; idx < 1024; idx += 256) {
        int t = idx >> 5, s2 = idx & 31;
        MshT[t*32 + s2] = g_Minv[(k*Ss + s2)*Ss + t];
    }
    __syncthreads();
    int w = threadIdx.x >> 5, lane = threadIdx.x & 31;
#pragma unroll
    for (int ii = 0; ii < 4; ii++) {
        int n = blockIdx.x*32 + w*4 + ii;
        float z = g_Zt[((size_t)k*Nn + n)*Ss + lane];
        float acc = 0.f;
#pragma unroll
        for (int t = 0; t < 32; t++)
            acc += MshT[t*32 + lane] * __shfl_sync(0xffffffffu, z, t);
        g_MinvZt[((size_t)k*Nn + n)*Ss + lane] = acc;
    }
}

__global__ void k_nbr(const float* __restrict__ adj) {
    int warp = threadIdx.x / 32, lane = threadIdx.x % 32;
    int i = blockIdx.x*4 + warp;
    int base = 0;
    const float4* rowv = (const float4*)(adj + (size_t)i*Nn);
    unsigned mlt = (1u << lane) - 1u;
    int* nb = g_nbr + (size_t)i*CAP;
#pragma unroll 4
    for (int it = 0; it < 32; it++) {
        float4 v = rowv[it*32 + lane];
        unsigned b0 = __ballot_sync(0xffffffffu, v.x > 0.5f);
        unsigned b1 = __ballot_sync(0xffffffffu, v.y > 0.5f);
        unsigned b2 = __ballot_sync(0xffffffffu, v.z > 0.5f);
        unsigned b3 = __ballot_sync(0xffffffffu, v.w > 0.5f);
        int pre = __popc(b0 & mlt) + __popc(b1 & mlt) + __popc(b2 & mlt) + __popc(b3 & mlt);
        int col = it*128 + 4*lane;
        int o = base + pre;
        if (v.x > 0.5f) { if (o < CAP) nb[o] = col;     o++; }
        if (v.y > 0.5f) { if (o < CAP) nb[o] = col + 1; o++; }
        if (v.z > 0.5f) { if (o < CAP) nb[o] = col + 2; o++; }
        if (v.w > 0.5f) { if (o < CAP) nb[o] = col + 3; o++; }
        base += __popc(b0) + __popc(b1) + __popc(b2) + __popc(b3);
    }
    if (lane == 0) g_cnt[i] = base < CAP ? base : CAP;
}

// group-of-32 sparse attention: lane=neighbor for scores, lane=s for V.
__global__ void k_attn() {
    int warp = threadIdx.x >> 5, lane = threadIdx.x & 31;
    int i = blockIdx.x*4 + warp;
    int k = blockIdx.y;
    const float* Zk = g_Zt + (size_t)k*Nn*Ss;
    const float* Mk = g_MinvZt + (size_t)k*Nn*Ss;
    float4 q4[8];
    const float4* qrow = (const float4*)(Zk + (size_t)i*Ss);
#pragma unroll
    for (int c = 0; c < 8; c++) q4[c] = qrow[c];
    int cnt = g_cnt[i];
    const int* nb = g_nbr + (size_t)i*CAP;
    float m = -3.0e38f, l = 0.f, o = 0.f;
    for (int t0 = 0; t0 < cnt; t0 += 32) {
        int t = t0 + lane;
        bool valid = (t < cnt);
        int j = valid ? nb[t] : 0;
        float p = -3.0e38f;
        if (valid) {
            const float4* kv = (const float4*)(Mk + (size_t)j*Ss);
            float s = 0.f;
#pragma unroll
            for (int c = 0; c < 8; c++) {
                float4 v = kv[c];
                s += q4[c].x*v.x + q4[c].y*v.y + q4[c].z*v.z + q4[c].w*v.w;
            }
            p = s;
        }
        float gmax = p;
#pragma unroll
        for (int off = 16; off > 0; off >>= 1)
            gmax = fmaxf(gmax, __shfl_xor_sync(0xffffffffu, gmax, off));
        float mn = fmaxf(m, gmax);
        float e = valid ? __expf(p - mn) : 0.f;
        float esum = e;
#pragma unroll
        for (int off = 16; off > 0; off >>= 1)
            esum += __shfl_xor_sync(0xffffffffu, esum, off);
        float sc = __expf(m - mn);
        float oadd = 0.f;
        int lim = cnt - t0; if (lim > 32) lim = 32;
        for (int jj = 0; jj < lim; jj++) {
            float a = __shfl_sync(0xffffffffu, e, jj);
            int jv = __shfl_sync(0xffffffffu, j, jj);
            oadd += a * Zk[(size_t)jv*Ss + lane];
        }
        o = o*sc + oadd;
        l = l*sc + esum;
        m = mn;
    }
    g_Zat[((size_t)k*Nn + i)*Ss + lane] = o / l;
}

__global__ void k_W(const float* __restrict__ U) {
    int k = blockIdx.x, d = threadIdx.x;
    __shared__ float Msh[Ss*Ss];
    for (int idx = threadIdx.x; idx < Ss*Ss; idx += 256)
        Msh[idx] = g_Minv[k*Ss*Ss + idx];
    __syncthreads();
    float acc[Ss];
#pragma unroll
    for (int t = 0; t < Ss; t++) acc[t] = 0.f;
    for (int s = 0; s < Ss; s++) {
        float u = U[((size_t)k*Dd + d)*Ss + s];
#pragma unroll
        for (int t = 0; t < Ss; t++) acc[t] += u * Msh[s*Ss + t];
    }
#pragma unroll
    for (int t = 0; t < Ss; t++) g_Wt[((size_t)k*Ss + t)*Dd + d] = acc[t];
}

__global__ void k_agg() {
    __shared__ float zat[32][128];
    int n0 = blockIdx.x*32;
    for (int idx = threadIdx.x; idx < 32*128; idx += 256) {
        int nn = idx / 128, kt = idx % 128;
        int k = kt / 32, t = kt % 32;
        zat[nn][kt] = g_Zat[((size_t)k*Nn + n0 + nn)*Ss + t];
    }
    __syncthreads();
    int d = threadIdx.x;
    float acc[32];
#pragma unroll
    for (int nn = 0; nn < 32; nn++) acc[nn] = 0.f;
    for (int kt = 0; kt < 128; kt++) {
        float w = g_Wt[(size_t)kt*Dd + d];
#pragma unroll
        for (int nn = 0; nn < 32; nn++) acc[nn] += w * zat[nn][kt];
    }
#pragma unroll
    for (int nn = 0; nn < 32; nn++) g_aggT[(size_t)(n0 + nn)*Dd + d] = acc[nn];
}

__global__ void k_thresh_tr(const float* __restrict__ H,
                            const float* __restrict__ lam,
                            const float* __restrict__ thrArr,
                            float* __restrict__ out) {
    __shared__ unsigned short tsh[64][66];
    int nb = blockIdx.x*64, db = blockIdx.y*64;
    float la = ETA*lam[0];
#pragma unroll
    for (int i = 0; i < 16; i++) {
        int idx = threadIdx.x + i*256;
        int r = idx >> 6, c = idx & 63;
        size_t g = (size_t)(nb + r)*Dd + db + c;
        float hh = H[g] + ETA*g_aggT[g] - la*g_LH[g];
        float a = fabsf(hh) - thrArr[db + c];
        float v = a > 0.f ? copysignf(a, hh) : 0.f;
        out[g] = v;
        tsh[c][r] = bf16b(v);
    }
    __syncthreads();
#pragma unroll
    for (int i = 0; i < 16; i++) {
        int idx = threadIdx.x + i*256;
        int r = idx >> 6, c = idx & 63;
        g_Hob[(size_t)(db + r)*Nn + nb + c] = tsh[r][c];
    }
}

__global__ void k_orth(const float* __restrict__ U) {
    int b = blockIdx.x, k = 0;
    while (b >= Kk - k) { b -= Kk - k; k++; }
    int l = k + b;
    int s = threadIdx.x / 32, e = threadIdx.x % 32;
    __shared__ float Uk[64][32], Ul[64][32];
    __shared__ float red[1024];
    float acc = 0.f;
    for (int d0 = 0; d0 < Dd; d0 += 64) {
        for (int idx = threadIdx.x; idx < 64*32; idx += 1024) {
            Uk[idx/32][idx%32] = U[((size_t)k*Dd + d0 + idx/32)*Ss + idx%32];
            Ul[idx/32][idx%32] = U[((size_t)l*Dd + d0 + idx/32)*Ss + idx%32];
        }
        __syncthreads();
#pragma unroll
        for (int dd = 0; dd < 64; dd++) acc += Uk[dd][s]*Ul[dd][e];
        __syncthreads();
    }
    float c;
    if (k == l) { float dl = acc - (s == e ? 1.f : 0.f); c = dl*dl; }
    else c = acc*acc;
    red[threadIdx.x] = c;
    __syncthreads();
    for (int st = 512; st > 0; st >>= 1) {
        if (threadIdx.x < st) red[threadIdx.x] += red[threadIdx.x + st];
        __syncthreads();
    }
    if (threadIdx.x == 0) g_orth[blockIdx.x] = red[0];
}

__global__ void k_scalars(float* __restrict__ out) {
    if (threadIdx.x == 0) {
        float o = 0.f;
        for (int i = 0; i < 10; i++) o += g_orth[i];
        out[(size_t)Nn*Dd] = o;
        float ls = 0.f;
        for (int i = 0; i < 128; i++) ls += g_part[i];
        out[(size_t)Nn*Dd + 1] = ls;
    }
}

// ---------------- launch: fork-join; gemm0 submitted 4th for ncu window -------
extern "C" void kernel_launch(void* const* d_in, const int* in_sizes, int n_in,
                              void* d_out, int out_size) {
    const float* H   = (const float*)d_in[0];
    const float* adj = (const float*)d_in[1];
    const float* L   = (const float*)d_in[2];
    const float* U   = (const float*)d_in[3];
    const float* lam = (const float*)d_in[4];
    const float* thr = (const float*)d_in[5];
    float* out = (float*)d_out;

    static cudaStream_t s2 = nullptr;
    static cudaEvent_t eFork = nullptr, eJoin = nullptr, eJoin2 = nullptr;
    static int init = 0;
    if (!init) {
        cudaFuncSetAttribute(k_gemm<0>, cudaFuncAttributeMaxDynamicSharedMemorySize, SMEMB);
        cudaFuncSetAttribute(k_gemm<1>, cudaFuncAttributeMaxDynamicSharedMemorySize, SMEMB);
        cudaStreamCreateWithFlags(&s2, cudaStreamNonBlocking);
        cudaEventCreateWithFlags(&eFork, cudaEventDisableTiming);
        cudaEventCreateWithFlags(&eJoin, cudaEventDisableTiming);
        cudaEventCreateWithFlags(&eJoin2, cudaEventDisableTiming);
        init = 1;
    }

    unsigned short* hbptr;
    cudaGetSymbolAddress((void**)&hbptr, g_Hb);

    cudaEventRecord(eFork, 0);
    cudaStreamWaitEvent(s2, eFork, 0);

    // submissions 1-4 (gemm0 is 4th launched kernel -> ncu -s 5 window)
    k_cvtLb<<<Nn*Nn/8/256, 256>>>(L);                         // 1 main
    k_tr<<<dim3(Nn/64, Dd/64), 256>>>(H, hbptr);              // 2 main
    k_Z<<<dim3(Nn/128, Kk), 128, 0, s2>>>(H, U);              // 3 s2
    k_gemm<0><<<dim3(Nn/BM, Dd/BN), 256, SMEMB>>>(nullptr);   // 4 main

    // rest of chain A on s2
    k_M<<<dim3(16, Kk), 1024, 0, s2>>>();
    k_invF<<<1, 256, 0, s2>>>();
    k_MinvZ<<<dim3(Nn/32, Kk), 256, 0, s2>>>();
    k_nbr<<<Nn/4, 128, 0, s2>>>(adj);
    k_attn<<<dim3(Nn/4, Kk), 128, 0, s2>>>();
    k_W<<<Kk, 256, 0, s2>>>(U);
    k_agg<<<Nn/32, 256, 0, s2>>>();
    cudaEventRecord(eJoin, s2);
    k_orth<<<10, 1024, 0, s2>>>(U);      // overlaps gemm2 on main
    cudaEventRecord(eJoin2, s2);

    // join, then tail on main
    cudaStreamWaitEvent(0, eJoin, 0);
    k_thresh_tr<<<dim3(Nn/64, Dd/64), 256>>>(H, lam, thr, out);
    k_gemm<1><<<dim3(Nn/BM, Dd/BN), 256, SMEMB>>>(out);
    cudaStreamWaitEvent(0, eJoin2, 0);
    k_scalars<<<1, 256>>>(out);
}

// round 16
// speedup vs baseline: 1.1130x; 1.0862x over previous
#include <cuda_runtime.h>
#include <cuda_bf16.h>
#include <cstdint>

#define Nn 4096
#define Dd 256
#define Ss 32
#define Kk 4
#define CAP 256
#define COEFF 0.03125f   /* S/(N*EPS^2) = 32/(4096*0.25) */
#define ETA 0.5f

// ---------------- scratch (no allocs allowed) ----------------
__device__ unsigned short g_Lb[(size_t)Nn*Nn];   // bf16 L (32MB)
__device__ unsigned short g_Hb[(size_t)Dd*Nn];   // bf16 H^T  [d][node]
__device__ unsigned short g_Hob[(size_t)Dd*Nn];  // bf16 Hout^T [d][node]
__device__ float g_Zt[Kk*Nn*Ss];
__device__ float g_MinvZt[Kk*Nn*Ss];
__device__ float g_Zat[Kk*Nn*Ss];
__device__ float g_Mpart[16*Kk*Ss*Ss];
__device__ float g_Minv[Kk*Ss*Ss];
__device__ float g_Wt[Kk*Ss*Dd];
__device__ int   g_nbr[Nn*CAP];
__device__ int   g_cnt[Nn];
__device__ float g_aggT[Nn*Dd];
__device__ float g_LH[Nn*Dd];
__device__ float g_part[128];
__device__ float g_orth[10];

__device__ __forceinline__ uint32_t smem_u32(const void* p) {
    uint32_t a;
    asm("{ .reg .u64 t; cvta.to.shared.u64 t, %1; cvt.u32.u64 %0, t; }" : "=r"(a) : "l"(p));
    return a;
}
__device__ __forceinline__ void cp16(uint32_t dst, const void* src) {
    asm volatile("cp.async.cg.shared.global [%0], [%1], 16;" :: "r"(dst), "l"(src) : "memory");
}
#define CP_COMMIT() asm volatile("cp.async.commit_group;" ::: "memory")
template<int N> __device__ __forceinline__ void cp_wait() {
    asm volatile("cp.async.wait_group %0;" :: "n"(N) : "memory");
}
__device__ __forceinline__ void ldm_x4(uint32_t (&r)[4], uint32_t addr) {
    asm volatile("ldmatrix.sync.aligned.m8n8.x4.shared.b16 {%0,%1,%2,%3}, [%4];"
        : "=r"(r[0]), "=r"(r[1]), "=r"(r[2]), "=r"(r[3]) : "r"(addr));
}
__device__ __forceinline__ void mma_bf16(float (&c)[4],
                                         uint32_t a0, uint32_t a1, uint32_t a2, uint32_t a3,
                                         uint32_t b0, uint32_t b1) {
    asm volatile(
        "mma.sync.aligned.m16n8k16.row.col.f32.bf16.bf16.f32 "
        "{%0,%1,%2,%3},{%4,%5,%6,%7},{%8,%9},{%0,%1,%2,%3};"
        : "+f"(c[0]), "+f"(c[1]), "+f"(c[2]), "+f"(c[3])
        : "r"(a0), "r"(a1), "r"(a2), "r"(a3), "r"(b0), "r"(b1));
}
__device__ __forceinline__ unsigned short bf16b(float x) {
    __nv_bfloat16 h = __float2bfloat16_rn(x);
    return *reinterpret_cast<unsigned short*>(&h);
}

// ================= prep kernels =================
__global__ void k_cvtLb(const float* __restrict__ L) {
    size_t i = ((size_t)blockIdx.x*256 + threadIdx.x)*8;
    float4 v0 = *(const float4*)(L + i);
    float4 v1 = *(const float4*)(L + i + 4);
    uint32_t p[4];
    p[0] = (uint32_t)bf16b(v0.x) | ((uint32_t)bf16b(v0.y) << 16);
    p[1] = (uint32_t)bf16b(v0.z) | ((uint32_t)bf16b(v0.w) << 16);
    p[2] = (uint32_t)bf16b(v1.x) | ((uint32_t)bf16b(v1.y) << 16);
    p[3] = (uint32_t)bf16b(v1.z) | ((uint32_t)bf16b(v1.w) << 16);
    *(uint4*)(g_Lb + i) = make_uint4(p[0], p[1], p[2], p[3]);
}

__global__ void k_tr(const float* __restrict__ src, unsigned short* __restrict__ dst) {
    __shared__ unsigned short t[64][66];
    int nb = blockIdx.x*64, db = blockIdx.y*64;
    int tid = threadIdx.x;
#pragma unroll
    for (int i = 0; i < 16; i++) {
        int idx = tid + i*256;
        int r = idx >> 6, c = idx & 63;
        t[c][r] = bf16b(src[(size_t)(nb + r)*Dd + db + c]);
    }
    __syncthreads();
#pragma unroll
    for (int i = 0; i < 16; i++) {
        int idx = tid + i*256;
        int r = idx >> 6, c = idx & 63;
        dst[(size_t)(db + r)*Nn + nb + c] = t[r][c];
    }
}

// ================= bf16 mma GEMM: C[4096x256] = L @ B =================
// BM=128, 6-stage cp.async ring (92KB smem) to cover DRAM/L2 latency.
#define BM 128
#define BN 64
#define BK 32
#define APITCH 80
#define BPITCH 80
#define A_BYTES (BM*APITCH)
#define B_BYTES (BN*BPITCH)
#define STG_B (A_BYTES + B_BYTES)
#define NSTG 6
#define SMEMB (NSTG*STG_B)        // 92160
#define NT (Nn/BK)

template<int MODE>
__global__ void __launch_bounds__(256, 1) k_gemm(const float* __restrict__ Hd) {
    extern __shared__ char sm[];
    int tid = threadIdx.x;
    int lane = tid & 31, warp = tid >> 5;
    int warpM = (warp & 3)*32, warpN = (warp >> 2)*32;
    int gid = lane >> 2, t4 = lane & 3;
    int bm = blockIdx.x*BM, bn = blockIdx.y*BN;
    const unsigned short* A  = g_Lb;
    const unsigned short* Bt = MODE ? g_Hob : g_Hb;
    uint32_t sb = smem_u32(sm);

    float acc[2][4][4] = {};

    int lr = (lane & 7) + ((lane >> 3) & 1)*8;
    int lc = (lane >> 4)*16;
    int bnr = (lane & 7) + ((lane >> 4) & 1)*8;
    int bco = ((lane >> 3) & 1)*16;

    int am0 = tid >> 2, ac0 = tid & 3;
    int am1 = (tid + 256) >> 2, ac1 = (tid + 256) & 3;
    int bm2 = tid >> 2, bc2 = tid & 3;

#define LOAD_STAGE(s, k0) do { \
    uint32_t base = sb + (s)*STG_B; \
    cp16(base + am0*APITCH + ac0*16, A + (size_t)(bm + am0)*Nn + (k0) + ac0*8); \
    cp16(base + am1*APITCH + ac1*16, A + (size_t)(bm + am1)*Nn + (k0) + ac1*8); \
    cp16(base + A_BYTES + bm2*BPITCH + bc2*16, Bt + (size_t)(bn + bm2)*Nn + (k0) + bc2*8); \
} while (0)

    // prologue: stages 0..NSTG-2 in flight
#pragma unroll
    for (int s = 0; s < NSTG-1; s++) {
        LOAD_STAGE(s, s*BK);
        CP_COMMIT();
    }

    int stage = 0, pstage = NSTG-1;
    for (int kt = 0; kt < NT; kt++) {
        cp_wait<NSTG-2>();
        __syncthreads();
        if (kt + NSTG-1 < NT) LOAD_STAGE(pstage, (kt+NSTG-1)*BK);
        CP_COMMIT();
        if (++pstage == NSTG) pstage = 0;

        uint32_t As = sb + stage*STG_B;
        uint32_t Bs = As + A_BYTES;
        if (++stage == NSTG) stage = 0;

        uint32_t a0[2][4], a1[2][4], b0[2][4], b1[2][4];
#pragma unroll
        for (int ks = 0; ks < 2; ks++) {
            ldm_x4(a0[ks], As + (warpM + lr)*APITCH + ks*32 + lc);
            ldm_x4(a1[ks], As + (warpM + 16 + lr)*APITCH + ks*32 + lc);
            ldm_x4(b0[ks], Bs + (warpN + bnr)*BPITCH + ks*32 + bco);
            ldm_x4(b1[ks], Bs + (warpN + 16 + bnr)*BPITCH + ks*32 + bco);
        }
#pragma unroll
        for (int ks = 0; ks < 2; ks++) {
            mma_bf16(acc[0][0], a0[ks][0], a0[ks][1], a0[ks][2], a0[ks][3], b0[ks][0], b0[ks][1]);
            mma_bf16(acc[1][0], a1[ks][0], a1[ks][1], a1[ks][2], a1[ks][3], b0[ks][0], b0[ks][1]);
            mma_bf16(acc[0][1], a0[ks][0], a0[ks][1], a0[ks][2], a0[ks][3], b0[ks][2], b0[ks][3]);
            mma_bf16(acc[1][1], a1[ks][0], a1[ks][1], a1[ks][2], a1[ks][3], b0[ks][2], b0[ks][3]);
            mma_bf16(acc[0][2], a0[ks][0], a0[ks][1], a0[ks][2], a0[ks][3], b1[ks][0], b1[ks][1]);
            mma_bf16(acc[1][2], a1[ks][0], a1[ks][1], a1[ks][2], a1[ks][3], b1[ks][0], b1[ks][1]);
            mma_bf16(acc[0][3], a0[ks][0], a0[ks][1], a0[ks][2], a0[ks][3], b1[ks][2], b1[ks][3]);
            mma_bf16(acc[1][3], a1[ks][0], a1[ks][1], a1[ks][2], a1[ks][3], b1[ks][2], b1[ks][3]);
        }
    }

    if (MODE == 0) {
#pragma unroll
        for (int mt = 0; mt < 2; mt++)
#pragma unroll
            for (int nt = 0; nt < 4; nt++) {
                int r0 = bm + warpM + mt*16 + gid;
                int c0 = bn + warpN + nt*8 + 2*t4;
                *(float2*)&g_LH[(size_t)r0*Dd + c0] = make_float2(acc[mt][nt][0], acc[mt][nt][1]);
                *(float2*)&g_LH[(size_t)(r0+8)*Dd + c0] = make_float2(acc[mt][nt][2], acc[mt][nt][3]);
            }
    } else {
        __shared__ float red[256];
        float part = 0.f;
#pragma unroll
        for (int mt = 0; mt < 2; mt++)
#pragma unroll
            for (int nt = 0; nt < 4; nt++) {
                int r0 = bm + warpM + mt*16 + gid;
                int c0 = bn + warpN + nt*8 + 2*t4;
                float2 h0 = *(const float2*)&Hd[(size_t)r0*Dd + c0];
                float2 h1 = *(const float2*)&Hd[(size_t)(r0+8)*Dd + c0];
                part += acc[mt][nt][0]*h0.x + acc[mt][nt][1]*h0.y
                      + acc[mt][nt][2]*h1.x + acc[mt][nt][3]*h1.y;
            }
        red[tid] = part;
        __syncthreads();
        for (int s = 128; s > 0; s >>= 1) {
            if (tid < s) red[tid] += red[tid + s];
            __syncthreads();
        }
        if (tid == 0) g_part[blockIdx.y*gridDim.x + blockIdx.x] = red[0];
    }
}

// ================= small kernels =================
__global__ void k_Z(const float* __restrict__ H, const float* __restrict__ U) {
    __shared__ float Ush[Dd*Ss];
    __shared__ float Hsh[128*17];
    int k = blockIdx.y;
    for (int idx = threadIdx.x; idx < Dd*Ss; idx += 128)
        Ush[idx] = U[k*Dd*Ss + idx];
    int nb = blockIdx.x*128;
    float acc[Ss];
#pragma unroll
    for (int s = 0; s < Ss; s++) acc[s] = 0.f;
    for (int d0 = 0; d0 < Dd; d0 += 16) {
        __syncthreads();
#pragma unroll
        for (int i = 0; i < 16; i++) {
            int idx = threadIdx.x + i*128;
            int node = idx >> 4, col = idx & 15;
            Hsh[node*17 + col] = H[(size_t)(nb + node)*Dd + d0 + col];
        }
        __syncthreads();
#pragma unroll
        for (int d = 0; d < 16; d++) {
            float h = Hsh[threadIdx.x*17 + d];
            const float* up = &Ush[(d0 + d)*Ss];
#pragma unroll
            for (int s = 0; s < Ss; s++) acc[s] += up[s]*h;
        }
    }
    float* zp = g_Zt + ((size_t)k*Nn + nb + threadIdx.x)*Ss;
#pragma unroll
    for (int s = 0; s < Ss; s++) zp[s] = acc[s];
}

__global__ void k_M() {
    int k = blockIdx.y;
    int chunk = blockIdx.x;
    __shared__ float zsh[32][33];
    int s = threadIdx.x / 32, t = threadIdx.x % 32;
    float acc = 0.f;
    int nbase = chunk*256;
    for (int n0 = 0; n0 < 256; n0 += 32) {
        zsh[threadIdx.x/32][threadIdx.x%32] =
            g_Zt[((size_t)k*Nn + nbase + n0 + threadIdx.x/32)*Ss + (threadIdx.x%32)];
        __syncthreads();
#pragma unroll
        for (int n = 0; n < 32; n++) acc += zsh[n][s]*zsh[n][t];
        __syncthreads();
    }
    g_Mpart[((size_t)chunk*Kk + k)*1024 + s*32 + t] = acc;
}

// fused Msum + register/shuffle Gauss-Jordan. 1 block, 256 threads.
__global__ void k_invF() {
    __shared__ float Msh[Kk*1024];
    int tid = threadIdx.x;
#pragma unroll
    for (int q = 0; q < Kk; q++) {
        for (int st = tid; st < 1024; st += 256) {
            float m = 0.f;
#pragma unroll
            for (int c = 0; c < 16; c++)
                m += g_Mpart[(size_t)(c*Kk + q)*1024 + st];
            int s = st >> 5, t = st & 31;
            Msh[q*1024 + st] = COEFF*m + (s == t ? 1.f : 0.f);
        }
    }
    __syncthreads();
    if (tid < 128) {
        int k = tid >> 5, j = tid & 31;
        float a[32], b[32];
#pragma unroll
        for (int r = 0; r < 32; r++) {
            a[r] = Msh[k*1024 + r*32 + j];
            b[r] = (r == j) ? 1.f : 0.f;
        }
#pragma unroll
        for (int p = 0; p < 32; p++) {
            float piv = __shfl_sync(0xffffffffu, a[p], p);
            float ip = 1.f / piv;
            a[p] *= ip; b[p] *= ip;
#pragma unroll
            for (int r = 0; r < 32; r++) {
                if (r == p) continue;
                float f = __shfl_sync(0xffffffffu, a[r], p);
                a[r] -= f*a[p];
                b[r] -= f*b[p];
            }
        }
#pragma unroll
        for (int r = 0; r < 32; r++) g_Minv[(k*32 + r)*32 + j] = b[r];
    }
}

__global__ void k_MinvZ() {
    int k = blockIdx.y;
    __shared__ float MshT[1024];
    for (int idx = threadIdx.x; idx < 1024; idx += 256) {
        int t = idx >> 5, s2 = idx & 31;
        MshT[t*32 + s2] = g_Minv[(k*Ss + s2)*Ss + t];
    }
    __syncthreads();
    int w = threadIdx.x >> 5, lane = threadIdx.x & 31;
#pragma unroll
    for (int ii = 0; ii < 4; ii++) {
        int n = blockIdx.x*32 + w*4 + ii;
        float z = g_Zt[((size_t)k*Nn + n)*Ss + lane];
        float acc = 0.f;
#pragma unroll
        for (int t = 0; t < 32; t++)
            acc += MshT[t*32 + lane] * __shfl_sync(0xffffffffu, z, t);
        g_MinvZt[((size_t)k*Nn + n)*Ss + lane] = acc;
    }
}

__global__ void k_nbr(const float* __restrict__ adj) {
    int warp = threadIdx.x / 32, lane = threadIdx.x % 32;
    int i = blockIdx.x*4 + warp;
    int base = 0;
    const float4* rowv = (const float4*)(adj + (size_t)i*Nn);
    unsigned mlt = (1u << lane) - 1u;
    int* nb = g_nbr + (size_t)i*CAP;
#pragma unroll 4
    for (int it = 0; it < 32; it++) {
        float4 v = rowv[it*32 + lane];
        unsigned b0 = __ballot_sync(0xffffffffu, v.x > 0.5f);
        unsigned b1 = __ballot_sync(0xffffffffu, v.y > 0.5f);
        unsigned b2 = __ballot_sync(0xffffffffu, v.z > 0.5f);
        unsigned b3 = __ballot_sync(0xffffffffu, v.w > 0.5f);
        int pre = __popc(b0 & mlt) + __popc(b1 & mlt) + __popc(b2 & mlt) + __popc(b3 & mlt);
        int col = it*128 + 4*lane;
        int o = base + pre;
        if (v.x > 0.5f) { if (o < CAP) nb[o] = col;     o++; }
        if (v.y > 0.5f) { if (o < CAP) nb[o] = col + 1; o++; }
        if (v.z > 0.5f) { if (o < CAP) nb[o] = col + 2; o++; }
        if (v.w > 0.5f) { if (o < CAP) nb[o] = col + 3; o++; }
        base += __popc(b0) + __popc(b1) + __popc(b2) + __popc(b3);
    }
    if (lane == 0) g_cnt[i] = base < CAP ? base : CAP;
}

// group-of-32 sparse attention: lane=neighbor for scores, lane=s for V.
__global__ void k_attn() {
    int warp = threadIdx.x >> 5, lane = threadIdx.x & 31;
    int i = blockIdx.x*4 + warp;
    int k = blockIdx.y;
    const float* Zk = g_Zt + (size_t)k*Nn*Ss;
    const float* Mk = g_MinvZt + (size_t)k*Nn*Ss;
    float4 q4[8];
    const float4* qrow = (const float4*)(Zk + (size_t)i*Ss);
#pragma unroll
    for (int c = 0; c < 8; c++) q4[c] = qrow[c];
    int cnt = g_cnt[i];
    const int* nb = g_nbr + (size_t)i*CAP;
    float m = -3.0e38f, l = 0.f, o = 0.f;
    for (int t0 = 0; t0 < cnt; t0 += 32) {
        int t = t0 + lane;
        bool valid = (t < cnt);
        int j = valid ? nb[t] : 0;
        float p = -3.0e38f;
        if (valid) {
            const float4* kv = (const float4*)(Mk + (size_t)j*Ss);
            float s = 0.f;
#pragma unroll
            for (int c = 0; c < 8; c++) {
                float4 v = kv[c];
                s += q4[c].x*v.x + q4[c].y*v.y + q4[c].z*v.z + q4[c].w*v.w;
            }
            p = s;
        }
        float gmax = p;
#pragma unroll
        for (int off = 16; off > 0; off >>= 1)
            gmax = fmaxf(gmax, __shfl_xor_sync(0xffffffffu, gmax, off));
        float mn = fmaxf(m, gmax);
        float e = valid ? __expf(p - mn) : 0.f;
        float esum = e;
#pragma unroll
        for (int off = 16; off > 0; off >>= 1)
            esum += __shfl_xor_sync(0xffffffffu, esum, off);
        float sc = __expf(m - mn);
        float oadd = 0.f;
        int lim = cnt - t0; if (lim > 32) lim = 32;
        for (int jj = 0; jj < lim; jj++) {
            float a = __shfl_sync(0xffffffffu, e, jj);
            int jv = __shfl_sync(0xffffffffu, j, jj);
            oadd += a * Zk[(size_t)jv*Ss + lane];
        }
        o = o*sc + oadd;
        l = l*sc + esum;
        m = mn;
    }
    g_Zat[((size_t)k*Nn + i)*Ss + lane] = o / l;
}

__global__ void k_W(const float* __restrict__ U) {
    int k = blockIdx.x, d = threadIdx.x;
    __shared__ float Msh[Ss*Ss];
    for (int idx = threadIdx.x; idx < Ss*Ss; idx += 256)
        Msh[idx] = g_Minv[k*Ss*Ss + idx];
    __syncthreads();
    float acc[Ss];
#pragma unroll
    for (int t = 0; t < Ss; t++) acc[t] = 0.f;
    for (int s = 0; s < Ss; s++) {
        float u = U[((size_t)k*Dd + d)*Ss + s];
#pragma unroll
        for (int t = 0; t < Ss; t++) acc[t] += u * Msh[s*Ss + t];
    }
#pragma unroll
    for (int t = 0; t < Ss; t++) g_Wt[((size_t)k*Ss + t)*Dd + d] = acc[t];
}

__global__ void k_agg() {
    __shared__ float zat[32][128];
    int n0 = blockIdx.x*32;
    for (int idx = threadIdx.x; idx < 32*128; idx += 256) {
        int nn = idx / 128, kt = idx % 128;
        int k = kt / 32, t = kt % 32;
        zat[nn][kt] = g_Zat[((size_t)k*Nn + n0 + nn)*Ss + t];
    }
    __syncthreads();
    int d = threadIdx.x;
    float acc[32];
#pragma unroll
    for (int nn = 0; nn < 32; nn++) acc[nn] = 0.f;
    for (int kt = 0; kt < 128; kt++) {
        float w = g_Wt[(size_t)kt*Dd + d];
#pragma unroll
        for (int nn = 0; nn < 32; nn++) acc[nn] += w * zat[nn][kt];
    }
#pragma unroll
    for (int nn = 0; nn < 32; nn++) g_aggT[(size_t)(n0 + nn)*Dd + d] = acc[nn];
}

__global__ void k_thresh_tr(const float* __restrict__ H,
                            const float* __restrict__ lam,
                            const float* __restrict__ thrArr,
                            float* __restrict__ out) {
    __shared__ unsigned short tsh[64][66];
    int nb = blockIdx.x*64, db = blockIdx.y*64;
    float la = ETA*lam[0];
#pragma unroll
    for (int i = 0; i < 16; i++) {
        int idx = threadIdx.x + i*256;
        int r = idx >> 6, c = idx & 63;
        size_t g = (size_t)(nb + r)*Dd + db + c;
        float hh = H[g] + ETA*g_aggT[g] - la*g_LH[g];
        float a = fabsf(hh) - thrArr[db + c];
        float v = a > 0.f ? copysignf(a, hh) : 0.f;
        out[g] = v;
        tsh[c][r] = bf16b(v);
    }
    __syncthreads();
#pragma unroll
    for (int i = 0; i < 16; i++) {
        int idx = threadIdx.x + i*256;
        int r = idx >> 6, c = idx & 63;
        g_Hob[(size_t)(db + r)*Nn + nb + c] = tsh[r][c];
    }
}

__global__ void k_orth(const float* __restrict__ U) {
    int b = blockIdx.x, k = 0;
    while (b >= Kk - k) { b -= Kk - k; k++; }
    int l = k + b;
    int s = threadIdx.x / 32, e = threadIdx.x % 32;
    __shared__ float Uk[64][32], Ul[64][32];
    __shared__ float red[1024];
    float acc = 0.f;
    for (int d0 = 0; d0 < Dd; d0 += 64) {
        for (int idx = threadIdx.x; idx < 64*32; idx += 1024) {
            Uk[idx/32][idx%32] = U[((size_t)k*Dd + d0 + idx/32)*Ss + idx%32];
            Ul[idx/32][idx%32] = U[((size_t)l*Dd + d0 + idx/32)*Ss + idx%32];
        }
        __syncthreads();
#pragma unroll
        for (int dd = 0; dd < 64; dd++) acc += Uk[dd][s]*Ul[dd][e];
        __syncthreads();
    }
    float c;
    if (k == l) { float dl = acc - (s == e ? 1.f : 0.f); c = dl*dl; }
    else c = acc*acc;
    red[threadIdx.x] = c;
    __syncthreads();
    for (int st = 512; st > 0; st >>= 1) {
        if (threadIdx.x < st) red[threadIdx.x] += red[threadIdx.x + st];
        __syncthreads();
    }
    if (threadIdx.x == 0) g_orth[blockIdx.x] = red[0];
}

__global__ void k_scalars(float* __restrict__ out) {
    if (threadIdx.x == 0) {
        float o = 0.f;
        for (int i = 0; i < 10; i++) o += g_orth[i];
        out[(size_t)Nn*Dd] = o;
        float ls = 0.f;
        for (int i = 0; i < 128; i++) ls += g_part[i];
        out[(size_t)Nn*Dd + 1] = ls;
    }
}

// ---------------- launch: exact R11 fork-join arrangement ----------------
extern "C" void kernel_launch(void* const* d_in, const int* in_sizes, int n_in,
                              void* d_out, int out_size) {
    const float* H   = (const float*)d_in[0];
    const float* adj = (const float*)d_in[1];
    const float* L   = (const float*)d_in[2];
    const float* U   = (const float*)d_in[3];
    const float* lam = (const float*)d_in[4];
    const float* thr = (const float*)d_in[5];
    float* out = (float*)d_out;

    static cudaStream_t s2 = nullptr;
    static cudaEvent_t eFork = nullptr, eJoin = nullptr, eJoin2 = nullptr;
    static int init = 0;
    if (!init) {
        cudaFuncSetAttribute(k_gemm<0>, cudaFuncAttributeMaxDynamicSharedMemorySize, SMEMB);
        cudaFuncSetAttribute(k_gemm<1>, cudaFuncAttributeMaxDynamicSharedMemorySize, SMEMB);
        cudaStreamCreateWithFlags(&s2, cudaStreamNonBlocking);
        cudaEventCreateWithFlags(&eFork, cudaEventDisableTiming);
        cudaEventCreateWithFlags(&eJoin, cudaEventDisableTiming);
        cudaEventCreateWithFlags(&eJoin2, cudaEventDisableTiming);
        init = 1;
    }

    unsigned short* hbptr;
    cudaGetSymbolAddress((void**)&hbptr, g_Hb);

    // fork: chain A (attention path) on s2
    cudaEventRecord(eFork, 0);
    cudaStreamWaitEvent(s2, eFork, 0);

    k_Z<<<dim3(Nn/128, Kk), 128, 0, s2>>>(H, U);
    k_M<<<dim3(16, Kk), 1024, 0, s2>>>();
    k_invF<<<1, 256, 0, s2>>>();
    k_MinvZ<<<dim3(Nn/32, Kk), 256, 0, s2>>>();
    k_nbr<<<Nn/4, 128, 0, s2>>>(adj);
    k_attn<<<dim3(Nn/4, Kk), 128, 0, s2>>>();
    k_W<<<Kk, 256, 0, s2>>>(U);
    k_agg<<<Nn/32, 256, 0, s2>>>();
    cudaEventRecord(eJoin, s2);
    k_orth<<<10, 1024, 0, s2>>>(U);      // overlaps gemm2 on main
    cudaEventRecord(eJoin2, s2);

    // chain B (L path) on main stream
    k_cvtLb<<<Nn*Nn/8/256, 256>>>(L);
    k_tr<<<dim3(Nn/64, Dd/64), 256>>>(H, hbptr);
    k_gemm<0><<<dim3(Nn/BM, Dd/BN), 256, SMEMB>>>(nullptr);

    // join, then tail
    cudaStreamWaitEvent(0, eJoin, 0);
    k_thresh_tr<<<dim3(Nn/64, Dd/64), 256>>>(H, lam, thr, out);
    k_gemm<1><<<dim3(Nn/BM, Dd/BN), 256, SMEMB>>>(out);
    cudaStreamWaitEvent(0, eJoin2, 0);
    k_scalars<<<1, 256>>>(out);
}